// round 2
// baseline (speedup 1.0000x reference)
#include <cuda_runtime.h>
#include <cstdint>
#include <cstddef>

// ---------------------------------------------------------------------------
// TreeRNNCell: out = tanh( mask*(x@W_in + b_in) + segsum(h[src]->dst)@W_aggr + b_aggr )
// N = 500000 nodes, E = 500000 edges, X = H = 128.
//
// Pipeline (3 kernels, stream-ordered, graph-capturable):
//   1) zero g_agg scratch            (256 MB __device__ global)
//   2) scatter: red.global.add.v4    (segment_sum of h rows along edges)
//   3) fused K=256 GEMM + bias + mask + tanh epilogue (FFMA2 f32x2 path)
//
// R1 fix: mask is materialized as int32 by the harness (bool -> i32); read it
// as int words, not bytes.
// ---------------------------------------------------------------------------

#define MAXN 500000
__device__ float g_agg[(size_t)MAXN * 128];

__device__ __forceinline__ unsigned long long pk(float x, float y) {
    unsigned long long r;
    asm("mov.b64 %0, {%1,%2};" : "=l"(r) : "f"(x), "f"(y));
    return r;
}
__device__ __forceinline__ void fma2(unsigned long long& d, unsigned long long a,
                                     unsigned long long b) {
    asm("fma.rn.f32x2 %0, %1, %2, %0;" : "+l"(d) : "l"(a), "l"(b));
}
__device__ __forceinline__ float2 unpk(unsigned long long p) {
    float2 v;
    asm("mov.b64 {%0,%1}, %2;" : "=f"(v.x), "=f"(v.y) : "l"(p));
    return v;
}
__device__ __forceinline__ float tanh_fast(float x) {
    float r;
    asm("tanh.approx.f32 %0, %1;" : "=f"(r) : "f"(x));
    return r;
}

// ---------------------------------------------------------------------------
// Kernel 1: zero the aggregation scratch
// ---------------------------------------------------------------------------
__global__ void zero_kernel(long long n4) {
    long long i = (long long)blockIdx.x * blockDim.x + threadIdx.x;
    long long stride = (long long)gridDim.x * blockDim.x;
    float4 z = make_float4(0.f, 0.f, 0.f, 0.f);
    float4* p = reinterpret_cast<float4*>(g_agg);
    for (; i < n4; i += stride) p[i] = z;
}

// ---------------------------------------------------------------------------
// Kernel 2: scatter-add  g_agg[dst] += h[src]  (one warp per edge)
// ---------------------------------------------------------------------------
__global__ void scatter_kernel(const float* __restrict__ h,
                               const int* __restrict__ src,
                               const int* __restrict__ dst, int E) {
    int warp = (blockIdx.x * blockDim.x + threadIdx.x) >> 5;
    int lane = threadIdx.x & 31;
    if (warp >= E) return;
    int s = __ldg(&src[warp]);
    int d = __ldg(&dst[warp]);
    const float4 v = __ldg(reinterpret_cast<const float4*>(h + (size_t)s * 128) + lane);
    float* p = g_agg + (size_t)d * 128 + lane * 4;
    asm volatile("red.global.add.v4.f32 [%0], {%1,%2,%3,%4};"
                 :: "l"(p), "f"(v.x), "f"(v.y), "f"(v.z), "f"(v.w)
                 : "memory");
}

// ---------------------------------------------------------------------------
// Kernel 3: fused stacked GEMM (K=256) + bias + mask + tanh
//   A = [x | agg]  (mask folded into x half at load time)
//   W = [W_in ; W_aggr]   (both resident in smem)
// Block: 256 threads, TM=128 rows, all 128 cols.
// Thread (tr = tid/32, tc = tid%32): rows tr*16..+15, cols tc*4..+3.
// ---------------------------------------------------------------------------
#define TM 128
#define ASH_STRIDE 132  // padded: float4-aligned, modest store conflicts only

__global__ void __launch_bounds__(256) gemm_kernel(
    const float* __restrict__ x,
    const float* __restrict__ Win, const float* __restrict__ bin,
    const float* __restrict__ Waggr, const float* __restrict__ baggr,
    const int* __restrict__ mask,
    float* __restrict__ out, int N) {
    extern __shared__ float sm[];
    float* Wsh = sm;                    // [256][128]
    float* Ash = sm + 256 * 128;        // [32][ASH_STRIDE]

    const int tid = threadIdx.x;
    const int tr = tid >> 5;   // 0..7  (warp id)
    const int tc = tid & 31;   // 0..31 (lane)
    const int row0 = blockIdx.x * TM;

    // Load stacked W into smem (coalesced float4)
    {
        const float4* w0 = reinterpret_cast<const float4*>(Win);
        const float4* w1 = reinterpret_cast<const float4*>(Waggr);
        float4* s0 = reinterpret_cast<float4*>(Wsh);
        float4* s1 = reinterpret_cast<float4*>(Wsh + 128 * 128);
#pragma unroll
        for (int i = 0; i < 16; i++) {
            s0[tid + i * 256] = w0[tid + i * 256];
            s1[tid + i * 256] = w1[tid + i * 256];
        }
    }

    // Per-row mask + validity (cached in regs). mask is int32 (bool -> i32).
    float mrow[16];
    int rvalid[16];
#pragma unroll
    for (int i = 0; i < 16; i++) {
        int r = row0 + tr * 16 + i;
        bool ok = (r < N);
        rvalid[i] = ok ? 1 : 0;
        mrow[i] = (ok && (mask[ok ? r : 0] != 0)) ? 1.f : 0.f;
    }

    unsigned long long acc[16][2];
#pragma unroll
    for (int i = 0; i < 16; i++) { acc[i][0] = 0ull; acc[i][1] = 0ull; }

    for (int kb = 0; kb < 8; kb++) {
        const bool isx = (kb < 4);
        const float* src = isx ? x : g_agg;
        const int koff = (kb & 3) * 32;

        // Load A chunk, transposed into Ash[kk][localrow]; mask folded for x half
#pragma unroll
        for (int i = 0; i < 16; i++) {
            int r = row0 + tr * 16 + i;
            float v = 0.f;
            if (rvalid[i]) {
                v = __ldg(&src[(size_t)r * 128 + koff + tc]);
                if (isx) v *= mrow[i];
            }
            Ash[tc * ASH_STRIDE + tr * 16 + i] = v;
        }
        __syncthreads();

#pragma unroll 4
        for (int kk = 0; kk < 32; kk++) {
            float4 b = *reinterpret_cast<const float4*>(&Wsh[(kb * 32 + kk) * 128 + tc * 4]);
            unsigned long long b01 = pk(b.x, b.y);
            unsigned long long b23 = pk(b.z, b.w);
            const float4* arow =
                reinterpret_cast<const float4*>(&Ash[kk * ASH_STRIDE + tr * 16]);
#pragma unroll
            for (int i4 = 0; i4 < 4; i4++) {
                float4 a4 = arow[i4];
                unsigned long long aa;
                aa = pk(a4.x, a4.x);
                fma2(acc[i4 * 4 + 0][0], aa, b01); fma2(acc[i4 * 4 + 0][1], aa, b23);
                aa = pk(a4.y, a4.y);
                fma2(acc[i4 * 4 + 1][0], aa, b01); fma2(acc[i4 * 4 + 1][1], aa, b23);
                aa = pk(a4.z, a4.z);
                fma2(acc[i4 * 4 + 2][0], aa, b01); fma2(acc[i4 * 4 + 2][1], aa, b23);
                aa = pk(a4.w, a4.w);
                fma2(acc[i4 * 4 + 3][0], aa, b01); fma2(acc[i4 * 4 + 3][1], aa, b23);
            }
        }
        __syncthreads();
    }

    // Epilogue: + mask*b_in + b_aggr, tanh, store
    float4 bi = *reinterpret_cast<const float4*>(&bin[tc * 4]);
    float4 ba = *reinterpret_cast<const float4*>(&baggr[tc * 4]);
#pragma unroll
    for (int i = 0; i < 16; i++) {
        int r = row0 + tr * 16 + i;
        if (!rvalid[i]) continue;
        float2 v01 = unpk(acc[i][0]);
        float2 v23 = unpk(acc[i][1]);
        float m = mrow[i];
        float4 o;
        o.x = tanh_fast(v01.x + m * bi.x + ba.x);
        o.y = tanh_fast(v01.y + m * bi.y + ba.y);
        o.z = tanh_fast(v23.x + m * bi.z + ba.z);
        o.w = tanh_fast(v23.y + m * bi.w + ba.w);
        *reinterpret_cast<float4*>(&out[(size_t)r * 128 + tc * 4]) = o;
    }
}

// ---------------------------------------------------------------------------
// Launch
// ---------------------------------------------------------------------------
extern "C" void kernel_launch(void* const* d_in, const int* in_sizes, int n_in,
                              void* d_out, int out_size) {
    const float* x     = (const float*)d_in[0];
    const float* h     = (const float*)d_in[1];
    const float* Win   = (const float*)d_in[2];
    const float* bin   = (const float*)d_in[3];
    const float* Waggr = (const float*)d_in[4];
    const float* baggr = (const float*)d_in[5];
    const int* mask    = (const int*)d_in[6];
    const int* esrc    = (const int*)d_in[7];
    const int* edst    = (const int*)d_in[8];
    float* out = (float*)d_out;

    const int N = in_sizes[0] / 128;
    const int E = in_sizes[7];

    const int smem_bytes = (256 * 128 + 32 * ASH_STRIDE) * (int)sizeof(float);
    cudaFuncSetAttribute(gemm_kernel, cudaFuncAttributeMaxDynamicSharedMemorySize,
                         smem_bytes);

    long long n4 = (long long)N * 128 / 4;
    zero_kernel<<<2048, 256>>>(n4);
    scatter_kernel<<<(E + 7) / 8, 256>>>(h, esrc, edst, E);
    gemm_kernel<<<(N + TM - 1) / TM, 256, smem_bytes>>>(x, Win, bin, Waggr, baggr,
                                                        mask, out, N);
}

// round 4
// speedup vs baseline: 1.7010x; 1.7010x over previous
#include <cuda_runtime.h>
#include <cuda_bf16.h>
#include <cstdint>
#include <cstddef>

// ---------------------------------------------------------------------------
// TreeRNNCell: out = tanh( mask*(x@W_in + b_in) + segsum(h[src]->dst)@W_aggr + b_aggr )
// N = 500000, E = 500000, X = H = 128.
//
// R3: GEMM on tensor cores via baseline PTX mma.sync (tcgen05 not available:
//     harness targets plain sm_103). bf16 hi/lo split, 3-term (hh+lh+hl),
//     fp32 accumulators held in registers; K=256 as two K=128 phases.
// ---------------------------------------------------------------------------

#define MAXN 500000
__device__ float g_agg[(size_t)MAXN * 128];
// 4 images: [WinT_hi, WinT_lo, WaggrT_hi, WaggrT_lo], each [128n][128k] bf16
__device__ __align__(16) unsigned int g_wimg[4 * 8192];

__device__ __forceinline__ float tanh_fast(float x) {
    float r; asm("tanh.approx.f32 %0, %1;" : "=f"(r) : "f"(x)); return r;
}
__device__ __forceinline__ uint32_t smem_u32(const void* p) {
    uint32_t a;
    asm("{ .reg .u64 t; cvta.to.shared.u64 t, %1; cvt.u32.u64 %0, t; }" : "=r"(a) : "l"(p));
    return a;
}
__device__ __forceinline__ uint32_t pack_split(float a, float b, uint32_t& lo) {
    __nv_bfloat16 ha = __float2bfloat16(a), hb = __float2bfloat16(b);
    __nv_bfloat16 la = __float2bfloat16(a - __bfloat162float(ha));
    __nv_bfloat16 lb = __float2bfloat16(b - __bfloat162float(hb));
    lo = ((uint32_t)__bfloat16_as_ushort(lb) << 16) | __bfloat16_as_ushort(la);
    return ((uint32_t)__bfloat16_as_ushort(hb) << 16) | __bfloat16_as_ushort(ha);
}

#define LDSM_X4(r0, r1, r2, r3, addr) \
    asm volatile("ldmatrix.sync.aligned.m8n8.x4.shared.b16 {%0,%1,%2,%3}, [%4];" \
                 : "=r"(r0), "=r"(r1), "=r"(r2), "=r"(r3) : "r"(addr))

#define MMA16816(acc, a, b0, b1) \
    asm volatile("mma.sync.aligned.m16n8k16.row.col.f32.bf16.bf16.f32 " \
                 "{%0,%1,%2,%3}, {%4,%5,%6,%7}, {%8,%9}, {%0,%1,%2,%3};" \
                 : "+f"((acc)[0]), "+f"((acc)[1]), "+f"((acc)[2]), "+f"((acc)[3]) \
                 : "r"((a)[0]), "r"((a)[1]), "r"((a)[2]), "r"((a)[3]), \
                   "r"(b0), "r"(b1))

// smem layout (bytes). Rows padded to 136 bf16 (272B) -> conflict-free ldmatrix.
#define ROWB 272u
#define IMGB (128u * ROWB)           // 34816 per image
#define SM_W(i) ((i) * IMGB)         // images 0..3
#define SM_AH (4u * IMGB)            // 139264
#define SM_AL (SM_AH + IMGB)         // 174080
#define SM_TOTAL (SM_AL + IMGB)      // 208896

// ---------------------------------------------------------------------------
// Kernel 0: build W^T bf16 hi/lo images (plain [n][k] row-major, k=128 each)
// ---------------------------------------------------------------------------
__global__ void prep_w(const float* __restrict__ Win, const float* __restrict__ Wag) {
    int n = blockIdx.x;     // output feature 0..127
    int kp = threadIdx.x;   // k-pair 0..63
    int k0 = kp * 2;
    float a0 = Win[k0 * 128 + n], a1 = Win[(k0 + 1) * 128 + n];
    float b0 = Wag[k0 * 128 + n], b1 = Wag[(k0 + 1) * 128 + n];
    uint32_t alo, blo;
    uint32_t ahi = pack_split(a0, a1, alo);
    uint32_t bhi = pack_split(b0, b1, blo);
    int idx = n * 64 + kp;
    g_wimg[0 * 8192 + idx] = ahi;
    g_wimg[1 * 8192 + idx] = alo;
    g_wimg[2 * 8192 + idx] = bhi;
    g_wimg[3 * 8192 + idx] = blo;
}

// ---------------------------------------------------------------------------
// Kernel 1: zero the aggregation scratch
// ---------------------------------------------------------------------------
__global__ void zero_kernel(long long n4) {
    long long i = (long long)blockIdx.x * blockDim.x + threadIdx.x;
    long long stride = (long long)gridDim.x * blockDim.x;
    float4 z = make_float4(0.f, 0.f, 0.f, 0.f);
    float4* p = reinterpret_cast<float4*>(g_agg);
    for (; i < n4; i += stride) p[i] = z;
}

// ---------------------------------------------------------------------------
// Kernel 2: scatter-add  g_agg[dst] += h[src]  (one warp per edge)
// ---------------------------------------------------------------------------
__global__ void scatter_kernel(const float* __restrict__ h,
                               const int* __restrict__ src,
                               const int* __restrict__ dst, int E) {
    int warp = (blockIdx.x * blockDim.x + threadIdx.x) >> 5;
    int lane = threadIdx.x & 31;
    if (warp >= E) return;
    int s = __ldg(&src[warp]);
    int d = __ldg(&dst[warp]);
    const float4 v = __ldg(reinterpret_cast<const float4*>(h + (size_t)s * 128) + lane);
    float* p = g_agg + (size_t)d * 128 + lane * 4;
    asm volatile("red.global.add.v4.f32 [%0], {%1,%2,%3,%4};"
                 :: "l"(p), "f"(v.x), "f"(v.y), "f"(v.z), "f"(v.w)
                 : "memory");
}

// ---------------------------------------------------------------------------
// Kernel 3: warp-MMA GEMM + tanh epilogue. One CTA = 128 rows x 128 cols.
// ---------------------------------------------------------------------------
__global__ void __launch_bounds__(256, 1) gemm_mma(
    const float* __restrict__ x, const float* __restrict__ bin,
    const float* __restrict__ baggr, const int* __restrict__ mask,
    float* __restrict__ out, int N) {
    extern __shared__ char smem[];
    const uint32_t sbase = smem_u32(smem);
    const int tid = threadIdx.x;
    const int wid = tid >> 5;
    const int lid = tid & 31;
    const int row0 = blockIdx.x * 128;

    // ---- copy W images (global, plain layout) -> smem (padded rows) ----
    {
        const uint4* src = reinterpret_cast<const uint4*>(g_wimg);
#pragma unroll
        for (int it = 0; it < 32; it++) {
            int idx = tid + it * 256;        // 8192 uint4 total
            int row = idx >> 4;              // 0..511 (img*128 + n)
            int j = idx & 15;
            int img = row >> 7, n = row & 127;
            *reinterpret_cast<uint4*>(smem + SM_W(img) + n * ROWB + j * 16) = src[idx];
        }
    }

    // ---- load + split x tile (mask folded) into AH/AL ----
    const int row_local = tid >> 1;          // 0..127
    const int cbase = (tid & 1) * 64;        // 0 or 64
    const int rg = row0 + row_local;
    const bool ok = (rg < N);
    const float mrow = (ok && (__ldg(&mask[ok ? rg : 0]) != 0)) ? 1.f : 0.f;
    {
        const float4* xs = reinterpret_cast<const float4*>(x + (size_t)(ok ? rg : 0) * 128 + cbase);
#pragma unroll
        for (int j = 0; j < 16; j++) {
            float4 v = ok ? __ldg(xs + j) : make_float4(0.f, 0.f, 0.f, 0.f);
            v.x *= mrow; v.y *= mrow; v.z *= mrow; v.w *= mrow;
            uint32_t lo01, lo23;
            uint32_t hi01 = pack_split(v.x, v.y, lo01);
            uint32_t hi23 = pack_split(v.z, v.w, lo23);
            uint32_t off = row_local * ROWB + (cbase + 4 * j) * 2;
            *reinterpret_cast<uint32_t*>(smem + SM_AH + off) = hi01;
            *reinterpret_cast<uint32_t*>(smem + SM_AH + off + 4) = hi23;
            *reinterpret_cast<uint32_t*>(smem + SM_AL + off) = lo01;
            *reinterpret_cast<uint32_t*>(smem + SM_AL + off + 4) = lo23;
        }
    }
    __syncthreads();

    // ---- accumulators: warp owns rows m0..m0+15, all 128 cols (16 n-tiles) ----
    const int m0 = wid * 16;
    float acc[16][4];
#pragma unroll
    for (int i = 0; i < 16; i++) { acc[i][0] = acc[i][1] = acc[i][2] = acc[i][3] = 0.f; }

    // ldmatrix lane-address components
    const int l8 = lid & 7;
    const int quad = lid >> 3;  // 0..3
    // A frag: row = m0 + l8 + (quad&1)*8 ; col = (quad>>1)*8
    const uint32_t a_lane_off =
        (uint32_t)((m0 + l8 + (quad & 1) * 8) * ROWB + ((quad >> 1) * 8) * 2);
    // B frag: row = n0 + l8 + (quad>>1)*8 ; col = (quad&1)*8
    const uint32_t b_lane_off =
        (uint32_t)((l8 + (quad >> 1) * 8) * ROWB + ((quad & 1) * 8) * 2);

#pragma unroll 1
    for (int phase = 0; phase < 2; phase++) {
        const uint32_t whi = sbase + SM_W(phase * 2);
        const uint32_t wlo = sbase + SM_W(phase * 2 + 1);
        const uint32_t ahb = sbase + SM_AH + a_lane_off;
        const uint32_t alb = sbase + SM_AL + a_lane_off;

#pragma unroll
        for (int ks = 0; ks < 8; ks++) {
            const uint32_t kb = (uint32_t)(ks * 32);  // k0*2 bytes
            uint32_t ah[4], al[4];
            LDSM_X4(ah[0], ah[1], ah[2], ah[3], ahb + kb);
            LDSM_X4(al[0], al[1], al[2], al[3], alb + kb);
#pragma unroll
            for (int g = 0; g < 4; g++) {
                const uint32_t nb = (uint32_t)(g * 32 * ROWB);
                uint32_t bh[8], bl[8];
                LDSM_X4(bh[0], bh[1], bh[2], bh[3], whi + b_lane_off + nb + kb);
                LDSM_X4(bh[4], bh[5], bh[6], bh[7], whi + b_lane_off + nb + 16 * ROWB + kb);
                LDSM_X4(bl[0], bl[1], bl[2], bl[3], wlo + b_lane_off + nb + kb);
                LDSM_X4(bl[4], bl[5], bl[6], bl[7], wlo + b_lane_off + nb + 16 * ROWB + kb);
                float* a0 = acc[g * 4 + 0];
                float* a1 = acc[g * 4 + 1];
                float* a2 = acc[g * 4 + 2];
                float* a3 = acc[g * 4 + 3];
                MMA16816(a0, ah, bh[0], bh[1]);
                MMA16816(a1, ah, bh[2], bh[3]);
                MMA16816(a2, ah, bh[4], bh[5]);
                MMA16816(a3, ah, bh[6], bh[7]);
                MMA16816(a0, al, bh[0], bh[1]);
                MMA16816(a1, al, bh[2], bh[3]);
                MMA16816(a2, al, bh[4], bh[5]);
                MMA16816(a3, al, bh[6], bh[7]);
                MMA16816(a0, ah, bl[0], bl[1]);
                MMA16816(a1, ah, bl[2], bl[3]);
                MMA16816(a2, ah, bl[4], bl[5]);
                MMA16816(a3, ah, bl[6], bl[7]);
            }
        }

        if (phase == 0) {
            // rewrite A tiles with agg
            __syncthreads();
            const float4* as =
                reinterpret_cast<const float4*>(g_agg + (size_t)(ok ? rg : 0) * 128 + cbase);
#pragma unroll
            for (int j = 0; j < 16; j++) {
                float4 v = ok ? __ldg(as + j) : make_float4(0.f, 0.f, 0.f, 0.f);
                uint32_t lo01, lo23;
                uint32_t hi01 = pack_split(v.x, v.y, lo01);
                uint32_t hi23 = pack_split(v.z, v.w, lo23);
                uint32_t off = row_local * ROWB + (cbase + 4 * j) * 2;
                *reinterpret_cast<uint32_t*>(smem + SM_AH + off) = hi01;
                *reinterpret_cast<uint32_t*>(smem + SM_AH + off + 4) = hi23;
                *reinterpret_cast<uint32_t*>(smem + SM_AL + off) = lo01;
                *reinterpret_cast<uint32_t*>(smem + SM_AL + off + 4) = lo23;
            }
            __syncthreads();
        }
    }

    // ---- epilogue: acc in regs -> bias + mask*bias + tanh -> gmem ----
    {
        const int tq = lid >> 2;   // 0..7
        const int t4 = lid & 3;    // 0..3
        const int r1 = row0 + m0 + tq;
        const int r2 = r1 + 8;
        const float m1 = (r1 < N && __ldg(&mask[r1 < N ? r1 : 0]) != 0) ? 1.f : 0.f;
        const float m2 = (r2 < N && __ldg(&mask[r2 < N ? r2 : 0]) != 0) ? 1.f : 0.f;
#pragma unroll
        for (int nt = 0; nt < 16; nt++) {
            const int c = nt * 8 + 2 * t4;
            const float bi0 = __ldg(&bin[c]), bi1 = __ldg(&bin[c + 1]);
            const float ba0 = __ldg(&baggr[c]), ba1 = __ldg(&baggr[c + 1]);
            if (r1 < N) {
                float2 o;
                o.x = tanh_fast(acc[nt][0] + m1 * bi0 + ba0);
                o.y = tanh_fast(acc[nt][1] + m1 * bi1 + ba1);
                *reinterpret_cast<float2*>(&out[(size_t)r1 * 128 + c]) = o;
            }
            if (r2 < N) {
                float2 o;
                o.x = tanh_fast(acc[nt][2] + m2 * bi0 + ba0);
                o.y = tanh_fast(acc[nt][3] + m2 * bi1 + ba1);
                *reinterpret_cast<float2*>(&out[(size_t)r2 * 128 + c]) = o;
            }
        }
    }
}

// ---------------------------------------------------------------------------
// Launch
// ---------------------------------------------------------------------------
extern "C" void kernel_launch(void* const* d_in, const int* in_sizes, int n_in,
                              void* d_out, int out_size) {
    const float* x     = (const float*)d_in[0];
    const float* h     = (const float*)d_in[1];
    const float* Win   = (const float*)d_in[2];
    const float* bin   = (const float*)d_in[3];
    const float* Waggr = (const float*)d_in[4];
    const float* baggr = (const float*)d_in[5];
    const int* mask    = (const int*)d_in[6];
    const int* esrc    = (const int*)d_in[7];
    const int* edst    = (const int*)d_in[8];
    float* out = (float*)d_out;

    const int N = in_sizes[0] / 128;
    const int E = in_sizes[7];

    static int smem_set = 0;
    if (!smem_set) {
        cudaFuncSetAttribute(gemm_mma, cudaFuncAttributeMaxDynamicSharedMemorySize,
                             (int)SM_TOTAL);
        smem_set = 1;
    }

    prep_w<<<128, 64>>>(Win, Waggr);
    long long n4 = (long long)N * 128 / 4;
    zero_kernel<<<2048, 256>>>(n4);
    scatter_kernel<<<(E + 7) / 8, 256>>>(h, esrc, edst, E);
    gemm_mma<<<(N + 127) / 128, 256, SM_TOTAL>>>(x, bin, baggr, mask, out, N);
}